// round 2
// baseline (speedup 1.0000x reference)
#include <cuda_runtime.h>
#include <cuda_bf16.h>

#define NCOL    4096
#define THREADS 1024
#define EPS_T   1.1754943508222875e-38f   // float32 tiny

// One CTA per row of 4096. 1024 threads x 4 elements (one float4 per input).
// K=16 softmax iterations executed as 8 fused rounds: reduce (S=Σw, Q=Σw²)
// once, derive S2 = S - Q/S analytically, apply two softmax steps.
// One __syncthreads per round; cross-warp reduce done redundantly by every
// warp from a parity-double-buffered partial array (no broadcast barrier).
__global__ void __launch_bounds__(THREADS, 2)
subset_op_kernel(const float* __restrict__ scores,
                 const float* __restrict__ gnoise,
                 float* __restrict__ out)
{
    const int tid  = threadIdx.x;
    const int lane = tid & 31;
    const int warp = tid >> 5;
    const size_t base = (size_t)blockIdx.x * (NCOL / 4) + tid;

    __shared__ float  redm[32];
    __shared__ float2 red2[2][32];

    // ---- load s0 = scores + g : 4 elements per thread ----
    float4 a = reinterpret_cast<const float4*>(scores)[base];
    float4 b = reinterpret_cast<const float4*>(gnoise)[base];
    float w0 = a.x + b.x, w1 = a.y + b.y, w2 = a.z + b.z, w3 = a.w + b.w;

    // ---- row max (stable exp), single barrier ----
    float m = fmaxf(fmaxf(w0, w1), fmaxf(w2, w3));
#pragma unroll
    for (int o = 16; o > 0; o >>= 1) m = fmaxf(m, __shfl_xor_sync(0xffffffffu, m, o));
    if (lane == 0) redm[warp] = m;
    __syncthreads();
    m = redm[lane];
#pragma unroll
    for (int o = 16; o > 0; o >>= 1) m = fmaxf(m, __shfl_xor_sync(0xffffffffu, m, o));

    // ---- w = exp(s0 - M): only per-element transcendental ----
    w0 = __expf(w0 - m); w1 = __expf(w1 - m);
    w2 = __expf(w2 - m); w3 = __expf(w3 - m);

    float k0 = 0.f, k1 = 0.f, k2 = 0.f, k3 = 0.f;

#pragma unroll
    for (int r = 0; r < 8; r++) {
        // local partial moments
        float p1 = (w0 + w1) + (w2 + w3);
        float p2 = fmaf(w0, w0, fmaf(w1, w1, fmaf(w2, w2, w3 * w3)));
        // warp reduce (two independent chains interleave)
#pragma unroll
        for (int o = 16; o > 0; o >>= 1) {
            p1 += __shfl_xor_sync(0xffffffffu, p1, o);
            p2 += __shfl_xor_sync(0xffffffffu, p2, o);
        }
        if (lane == 0) red2[r & 1][warp] = make_float2(p1, p2);
        __syncthreads();
        // every warp reduces all 32 partials itself (no second barrier)
        float2 q = red2[r & 1][lane];
        float s1 = q.x, s2 = q.y;
#pragma unroll
        for (int o = 16; o > 0; o >>= 1) {
            s1 += __shfl_xor_sync(0xffffffffu, s1, o);
            s2 += __shfl_xor_sync(0xffffffffu, s2, o);
        }
        const float inv1 = __frcp_rn(s1);
        const float S2   = fmaf(-s2, inv1, s1);   // S - Q/S = Σ w(1 - w/S)
        const float inv2 = __frcp_rn(S2);

        float t;
        // step A (uses S)
        t = fmaf(-w0, inv1, 1.f); k0 = fmaf(w0, inv1, k0); w0 *= fmaxf(t, EPS_T);
        t = fmaf(-w1, inv1, 1.f); k1 = fmaf(w1, inv1, k1); w1 *= fmaxf(t, EPS_T);
        t = fmaf(-w2, inv1, 1.f); k2 = fmaf(w2, inv1, k2); w2 *= fmaxf(t, EPS_T);
        t = fmaf(-w3, inv1, 1.f); k3 = fmaf(w3, inv1, k3); w3 *= fmaxf(t, EPS_T);
        // step B (uses S2)
        t = fmaf(-w0, inv2, 1.f); k0 = fmaf(w0, inv2, k0); w0 *= fmaxf(t, EPS_T);
        t = fmaf(-w1, inv2, 1.f); k1 = fmaf(w1, inv2, k1); w1 *= fmaxf(t, EPS_T);
        t = fmaf(-w2, inv2, 1.f); k2 = fmaf(w2, inv2, k2); w2 *= fmaxf(t, EPS_T);
        t = fmaf(-w3, inv2, 1.f); k3 = fmaf(w3, inv2, k3); w3 *= fmaxf(t, EPS_T);
    }

    // ---- store khot ----
    float4 r4;
    r4.x = k0; r4.y = k1; r4.z = k2; r4.w = k3;
    reinterpret_cast<float4*>(out)[base] = r4;
}

extern "C" void kernel_launch(void* const* d_in, const int* in_sizes, int n_in,
                              void* d_out, int out_size)
{
    const float* scores = (const float*)d_in[0];
    const float* gnoise = (const float*)d_in[1];
    float* out = (float*)d_out;

    const int total = in_sizes[0];        // 4 * 2048 * 4096
    const int rows  = total / NCOL;       // 8192

    subset_op_kernel<<<rows, THREADS>>>(scores, gnoise, out);
}

// round 4
// speedup vs baseline: 1.2522x; 1.2522x over previous
#include <cuda_runtime.h>
#include <cuda_bf16.h>

#define NCOL    4096
#define THREADS 256
#define EPS_T   1.1754943508222875e-38f   // float32 tiny

// One CTA (256 threads) per row of 4096: 16 elements/thread (4 float4 loads).
// K=16 softmax iterations as 8 fused rounds: reduce (S=Σw, Q=Σw²) once,
// S2 = S - Q/S analytically, apply two softmax steps per round.
// Reduction: 8-warp partials -> warp 0 reduces + computes both reciprocals ->
// float2 broadcast. Two cheap nw=8 barriers/round; 4 CTAs/SM overlap.
__global__ void __launch_bounds__(THREADS, 4)
subset_op_kernel(const float* __restrict__ scores,
                 const float* __restrict__ gnoise,
                 float* __restrict__ out)
{
    const int tid  = threadIdx.x;
    const int lane = tid & 31;
    const int warp = tid >> 5;
    const size_t rb = (size_t)blockIdx.x * (NCOL / 4);
    const float4* s4 = reinterpret_cast<const float4*>(scores) + rb;
    const float4* g4 = reinterpret_cast<const float4*>(gnoise) + rb;
    float4*       o4 = reinterpret_cast<float4*>(out)          + rb;

    __shared__ float2 redp[8];
    __shared__ float2 bc;

    // ---- load s0 = scores + g : 16 elements per thread ----
    float w[16];
#pragma unroll
    for (int j = 0; j < 4; j++) {
        float4 a = s4[tid + j * THREADS];
        float4 b = g4[tid + j * THREADS];
        w[4*j+0] = a.x + b.x; w[4*j+1] = a.y + b.y;
        w[4*j+2] = a.z + b.z; w[4*j+3] = a.w + b.w;
    }

    // ---- row max (one-time) ----
    float m = w[0];
#pragma unroll
    for (int j = 1; j < 16; j++) m = fmaxf(m, w[j]);
#pragma unroll
    for (int o = 16; o > 0; o >>= 1) m = fmaxf(m, __shfl_xor_sync(0xffffffffu, m, o));
    if (lane == 0) redp[warp].x = m;
    __syncthreads();
    if (warp == 0) {
        float v = redp[lane & 7].x;
#pragma unroll
        for (int o = 4; o > 0; o >>= 1) v = fmaxf(v, __shfl_xor_sync(0xffffffffu, v, o));
        if (lane == 0) bc.x = v;
    }
    __syncthreads();
    const float M = bc.x;

    // ---- w = exp(s0 - M): only per-element transcendental ----
#pragma unroll
    for (int j = 0; j < 16; j++) w[j] = __expf(w[j] - M);

    float kh[16];
#pragma unroll
    for (int j = 0; j < 16; j++) kh[j] = 0.f;

#pragma unroll
    for (int r = 0; r < 8; r++) {
        // local partial moments (trees over 16 elems: good ILP)
        float p1 = 0.f, p2 = 0.f;
        {
            float a0 = (w[0]+w[1]) + (w[2]+w[3]);
            float a1 = (w[4]+w[5]) + (w[6]+w[7]);
            float a2 = (w[8]+w[9]) + (w[10]+w[11]);
            float a3 = (w[12]+w[13]) + (w[14]+w[15]);
            p1 = (a0 + a1) + (a2 + a3);
            float b0 = fmaf(w[0],w[0], fmaf(w[1],w[1], fmaf(w[2],w[2], w[3]*w[3])));
            float b1 = fmaf(w[4],w[4], fmaf(w[5],w[5], fmaf(w[6],w[6], w[7]*w[7])));
            float b2 = fmaf(w[8],w[8], fmaf(w[9],w[9], fmaf(w[10],w[10], w[11]*w[11])));
            float b3 = fmaf(w[12],w[12], fmaf(w[13],w[13], fmaf(w[14],w[14], w[15]*w[15])));
            p2 = (b0 + b1) + (b2 + b3);
        }
        // intra-warp reduce (two interleaved chains)
#pragma unroll
        for (int o = 16; o > 0; o >>= 1) {
            p1 += __shfl_xor_sync(0xffffffffu, p1, o);
            p2 += __shfl_xor_sync(0xffffffffu, p2, o);
        }
        if (lane == 0) redp[warp] = make_float2(p1, p2);
        __syncthreads();
        // warp 0 only: reduce 8 partials, compute both reciprocals, broadcast
        if (warp == 0) {
            float2 q = redp[lane & 7];
            float s1 = q.x, s2 = q.y;
#pragma unroll
            for (int o = 4; o > 0; o >>= 1) {
                s1 += __shfl_xor_sync(0xffffffffu, s1, o);
                s2 += __shfl_xor_sync(0xffffffffu, s2, o);
            }
            if (lane == 0) {
                float inv1 = __frcp_rn(s1);
                float S2   = fmaf(-s2, inv1, s1);   // S - Q/S = Σ w(1 - w/S)
                bc = make_float2(inv1, __frcp_rn(S2));
            }
        }
        __syncthreads();
        const float inv1 = bc.x;
        const float inv2 = bc.y;

        // two fused softmax steps, 16 elements each
#pragma unroll
        for (int j = 0; j < 16; j++) {
            float t = fmaf(-w[j], inv1, 1.f);
            kh[j] = fmaf(w[j], inv1, kh[j]);
            w[j] *= fmaxf(t, EPS_T);
        }
#pragma unroll
        for (int j = 0; j < 16; j++) {
            float t = fmaf(-w[j], inv2, 1.f);
            kh[j] = fmaf(w[j], inv2, kh[j]);
            w[j] *= fmaxf(t, EPS_T);
        }
    }

    // ---- store khot ----
#pragma unroll
    for (int j = 0; j < 4; j++) {
        float4 r4;
        r4.x = kh[4*j+0]; r4.y = kh[4*j+1];
        r4.z = kh[4*j+2]; r4.w = kh[4*j+3];
        o4[tid + j * THREADS] = r4;
    }
}

extern "C" void kernel_launch(void* const* d_in, const int* in_sizes, int n_in,
                              void* d_out, int out_size)
{
    const float* scores = (const float*)d_in[0];
    const float* gnoise = (const float*)d_in[1];
    float* out = (float*)d_out;

    const int total = in_sizes[0];        // 4 * 2048 * 4096
    const int rows  = total / NCOL;       // 8192

    subset_op_kernel<<<rows, THREADS>>>(scores, gnoise, out);
}

// round 8
// speedup vs baseline: 2.3042x; 1.8401x over previous
#include <cuda_runtime.h>
#include <cuda_bf16.h>

#define NCOL    4096
#define THREADS 256
#define EPS_T   1.1754943508222875e-38f   // float32 tiny

typedef unsigned long long u64;

// ---- Blackwell packed f32x2 helpers (one instruction, two fp32 lanes) ----
__device__ __forceinline__ u64 pk2(float lo, float hi) {
    u64 r; asm("mov.b64 %0, {%1, %2};" : "=l"(r) : "f"(lo), "f"(hi)); return r;
}
__device__ __forceinline__ void upk2(u64 v, float& lo, float& hi) {
    asm("mov.b64 {%0, %1}, %2;" : "=f"(lo), "=f"(hi) : "l"(v));
}
__device__ __forceinline__ u64 fma2(u64 a, u64 b, u64 c) {
    u64 d; asm("fma.rn.f32x2 %0, %1, %2, %3;" : "=l"(d) : "l"(a), "l"(b), "l"(c)); return d;
}
__device__ __forceinline__ u64 mul2(u64 a, u64 b) {
    u64 d; asm("mul.rn.f32x2 %0, %1, %2;" : "=l"(d) : "l"(a), "l"(b)); return d;
}
__device__ __forceinline__ u64 add2(u64 a, u64 b) {
    u64 d; asm("add.rn.f32x2 %0, %1, %2;" : "=l"(d) : "l"(a), "l"(b)); return d;
}

// One CTA (256 threads) per row of 4096: 16 elements/thread held as 8 packed
// f32x2 registers. K=16 softmax iterations as 8 fused rounds (S2 = S - Q/S).
// All per-element math uses packed FFMA2/FMUL2/FADD2 (fma pipe, 2 lanes/instr);
// only the EPS clamp runs scalar FMNMX on the idle alu pipe.
__global__ void __launch_bounds__(THREADS, 4)
subset_op_kernel(const float* __restrict__ scores,
                 const float* __restrict__ gnoise,
                 float* __restrict__ out)
{
    const int tid  = threadIdx.x;
    const int lane = tid & 31;
    const int warp = tid >> 5;
    const size_t rb = (size_t)blockIdx.x * (NCOL / 4);
    const float4* s4 = reinterpret_cast<const float4*>(scores) + rb;
    const float4* g4 = reinterpret_cast<const float4*>(gnoise) + rb;
    float4*       o4 = reinterpret_cast<float4*>(out)          + rb;

    __shared__ float2 redp[8];
    __shared__ float2 bc;

    // ---- load s0 = scores + g : 16 elements per thread (scalar staging) ----
    float s[16];
#pragma unroll
    for (int j = 0; j < 4; j++) {
        float4 a = s4[tid + j * THREADS];
        float4 b = g4[tid + j * THREADS];
        s[4*j+0] = a.x + b.x; s[4*j+1] = a.y + b.y;
        s[4*j+2] = a.z + b.z; s[4*j+3] = a.w + b.w;
    }

    // ---- row max (one-time) ----
    float m = s[0];
#pragma unroll
    for (int j = 1; j < 16; j++) m = fmaxf(m, s[j]);
#pragma unroll
    for (int o = 16; o > 0; o >>= 1) m = fmaxf(m, __shfl_xor_sync(0xffffffffu, m, o));
    if (lane == 0) redp[warp].x = m;
    __syncthreads();
    if (warp == 0) {
        float v = redp[lane & 7].x;
#pragma unroll
        for (int o = 4; o > 0; o >>= 1) v = fmaxf(v, __shfl_xor_sync(0xffffffffu, v, o));
        if (lane == 0) bc.x = v;
    }
    __syncthreads();
    const float M = bc.x;

    // ---- w = exp(s0 - M), pack into 8 f32x2 registers ----
    u64 w2[8], kh2[8];
#pragma unroll
    for (int i = 0; i < 8; i++) {
        w2[i]  = pk2(__expf(s[2*i] - M), __expf(s[2*i+1] - M));
        kh2[i] = 0ull;   // (0.f, 0.f)
    }

    const u64 ones2 = pk2(1.f, 1.f);

#pragma unroll
    for (int r = 0; r < 8; r++) {
        // ---- packed moments: p1 = Σw, p2 = Σw² ----
        u64 a1 = add2(w2[0], w2[1]);
        u64 a2 = add2(w2[2], w2[3]);
        u64 a3 = add2(w2[4], w2[5]);
        u64 a4 = add2(w2[6], w2[7]);
        u64 p1p = add2(add2(a1, a2), add2(a3, a4));

        u64 q1 = mul2(w2[0], w2[0]);
        q1 = fma2(w2[1], w2[1], q1);
        q1 = fma2(w2[2], w2[2], q1);
        q1 = fma2(w2[3], w2[3], q1);
        q1 = fma2(w2[4], w2[4], q1);
        q1 = fma2(w2[5], w2[5], q1);
        q1 = fma2(w2[6], w2[6], q1);
        u64 p2p = fma2(w2[7], w2[7], q1);

        float p1a, p1b, p2a, p2b;
        upk2(p1p, p1a, p1b);
        upk2(p2p, p2a, p2b);
        float p1 = p1a + p1b;
        float p2 = p2a + p2b;

        // ---- intra-warp reduce (two interleaved chains) ----
#pragma unroll
        for (int o = 16; o > 0; o >>= 1) {
            p1 += __shfl_xor_sync(0xffffffffu, p1, o);
            p2 += __shfl_xor_sync(0xffffffffu, p2, o);
        }
        if (lane == 0) redp[warp] = make_float2(p1, p2);
        __syncthreads();
        // ---- warp 0: reduce 8 partials, both reciprocals, broadcast ----
        if (warp == 0) {
            float2 q = redp[lane & 7];
            float s1 = q.x, s2 = q.y;
#pragma unroll
            for (int o = 4; o > 0; o >>= 1) {
                s1 += __shfl_xor_sync(0xffffffffu, s1, o);
                s2 += __shfl_xor_sync(0xffffffffu, s2, o);
            }
            if (lane == 0) {
                float inv1 = __frcp_rn(s1);
                float S2   = fmaf(-s2, inv1, s1);   // S - Q/S = Σ w(1 - w/S)
                bc = make_float2(inv1, __frcp_rn(S2));
            }
        }
        __syncthreads();
        const float inv1 = bc.x;
        const float inv2 = bc.y;

        const u64 iv1  = pk2(inv1, inv1);
        const u64 niv1 = pk2(-inv1, -inv1);
        const u64 iv2  = pk2(inv2, inv2);
        const u64 niv2 = pk2(-inv2, -inv2);

        // ---- step A (uses 1/S) ----
#pragma unroll
        for (int i = 0; i < 8; i++) {
            u64 t2 = fma2(w2[i], niv1, ones2);       // 1 - w/S
            kh2[i] = fma2(w2[i], iv1, kh2[i]);       // khot += w/S
            float t0, t1;
            upk2(t2, t0, t1);
            t0 = fmaxf(t0, EPS_T);                   // scalar clamp on alu pipe
            t1 = fmaxf(t1, EPS_T);
            w2[i] = mul2(w2[i], pk2(t0, t1));
        }
        // ---- step B (uses 1/S2) ----
#pragma unroll
        for (int i = 0; i < 8; i++) {
            u64 t2 = fma2(w2[i], niv2, ones2);
            kh2[i] = fma2(w2[i], iv2, kh2[i]);
            float t0, t1;
            upk2(t2, t0, t1);
            t0 = fmaxf(t0, EPS_T);
            t1 = fmaxf(t1, EPS_T);
            w2[i] = mul2(w2[i], pk2(t0, t1));
        }
    }

    // ---- store khot ----
#pragma unroll
    for (int j = 0; j < 4; j++) {
        float4 r4;
        upk2(kh2[2*j],   r4.x, r4.y);
        upk2(kh2[2*j+1], r4.z, r4.w);
        o4[tid + j * THREADS] = r4;
    }
}

extern "C" void kernel_launch(void* const* d_in, const int* in_sizes, int n_in,
                              void* d_out, int out_size)
{
    const float* scores = (const float*)d_in[0];
    const float* gnoise = (const float*)d_in[1];
    float* out = (float*)d_out;

    const int total = in_sizes[0];        // 4 * 2048 * 4096
    const int rows  = total / NCOL;       // 8192

    subset_op_kernel<<<rows, THREADS>>>(scores, gnoise, out);
}

// round 9
// speedup vs baseline: 2.4684x; 1.0713x over previous
#include <cuda_runtime.h>
#include <cuda_bf16.h>

#define NCOL    4096
#define THREADS 256

typedef unsigned long long u64;

// ---- Blackwell packed f32x2 helpers (one instruction, two fp32 lanes) ----
__device__ __forceinline__ u64 pk2(float lo, float hi) {
    u64 r; asm("mov.b64 %0, {%1, %2};" : "=l"(r) : "f"(lo), "f"(hi)); return r;
}
__device__ __forceinline__ void upk2(u64 v, float& lo, float& hi) {
    asm("mov.b64 {%0, %1}, %2;" : "=f"(lo), "=f"(hi) : "l"(v));
}
__device__ __forceinline__ u64 fma2(u64 a, u64 b, u64 c) {
    u64 d; asm("fma.rn.f32x2 %0, %1, %2, %3;" : "=l"(d) : "l"(a), "l"(b), "l"(c)); return d;
}
__device__ __forceinline__ u64 mul2(u64 a, u64 b) {
    u64 d; asm("mul.rn.f32x2 %0, %1, %2;" : "=l"(d) : "l"(a), "l"(b)); return d;
}
__device__ __forceinline__ u64 add2(u64 a, u64 b) {
    u64 d; asm("add.rn.f32x2 %0, %1, %2;" : "=l"(d) : "l"(a), "l"(b)); return d;
}

// One CTA (256 threads) per row of 4096: 16 elements/thread held as 8 packed
// f32x2 registers. K=16 softmax iterations as 8 fused rounds (S2 = S - Q/S).
// Inner step is now 3 pure packed fma-pipe instructions per pair (fma2, fma2,
// mul2) with NO scalar clamp: t = 1 - w/S >= -2ulp always, so the unclamped
// update deviates from the EPS-clamped reference by O(1e-7) at most.
__global__ void __launch_bounds__(THREADS, 4)
subset_op_kernel(const float* __restrict__ scores,
                 const float* __restrict__ gnoise,
                 float* __restrict__ out)
{
    const int tid  = threadIdx.x;
    const int lane = tid & 31;
    const int warp = tid >> 5;
    const size_t rb = (size_t)blockIdx.x * (NCOL / 4);
    const float4* s4 = reinterpret_cast<const float4*>(scores) + rb;
    const float4* g4 = reinterpret_cast<const float4*>(gnoise) + rb;
    float4*       o4 = reinterpret_cast<float4*>(out)          + rb;

    __shared__ float2 redp[8];
    __shared__ float2 bc;

    // ---- load s0 = scores + g : 16 elements per thread (scalar staging) ----
    float s[16];
#pragma unroll
    for (int j = 0; j < 4; j++) {
        float4 a = s4[tid + j * THREADS];
        float4 b = g4[tid + j * THREADS];
        s[4*j+0] = a.x + b.x; s[4*j+1] = a.y + b.y;
        s[4*j+2] = a.z + b.z; s[4*j+3] = a.w + b.w;
    }

    // ---- row max (one-time) ----
    float m = s[0];
#pragma unroll
    for (int j = 1; j < 16; j++) m = fmaxf(m, s[j]);
#pragma unroll
    for (int o = 16; o > 0; o >>= 1) m = fmaxf(m, __shfl_xor_sync(0xffffffffu, m, o));
    if (lane == 0) redp[warp].x = m;
    __syncthreads();
    if (warp == 0) {
        float v = redp[lane & 7].x;
#pragma unroll
        for (int o = 4; o > 0; o >>= 1) v = fmaxf(v, __shfl_xor_sync(0xffffffffu, v, o));
        if (lane == 0) bc.x = v;
    }
    __syncthreads();
    const float M = bc.x;

    // ---- w = exp(s0 - M), pack into 8 f32x2 registers ----
    u64 w2[8], kh2[8];
#pragma unroll
    for (int i = 0; i < 8; i++) {
        w2[i]  = pk2(__expf(s[2*i] - M), __expf(s[2*i+1] - M));
        kh2[i] = 0ull;   // (0.f, 0.f)
    }

    const u64 ones2 = pk2(1.f, 1.f);

#pragma unroll
    for (int r = 0; r < 8; r++) {
        // ---- packed moments: p1 = Σw, p2 = Σw² ----
        u64 a1 = add2(w2[0], w2[1]);
        u64 a2 = add2(w2[2], w2[3]);
        u64 a3 = add2(w2[4], w2[5]);
        u64 a4 = add2(w2[6], w2[7]);
        u64 p1p = add2(add2(a1, a2), add2(a3, a4));

        u64 q1 = mul2(w2[0], w2[0]);
        q1 = fma2(w2[1], w2[1], q1);
        q1 = fma2(w2[2], w2[2], q1);
        q1 = fma2(w2[3], w2[3], q1);
        q1 = fma2(w2[4], w2[4], q1);
        q1 = fma2(w2[5], w2[5], q1);
        q1 = fma2(w2[6], w2[6], q1);
        u64 p2p = fma2(w2[7], w2[7], q1);

        float p1a, p1b, p2a, p2b;
        upk2(p1p, p1a, p1b);
        upk2(p2p, p2a, p2b);
        float p1 = p1a + p1b;
        float p2 = p2a + p2b;

        // ---- intra-warp reduce (two interleaved chains) ----
#pragma unroll
        for (int o = 16; o > 0; o >>= 1) {
            p1 += __shfl_xor_sync(0xffffffffu, p1, o);
            p2 += __shfl_xor_sync(0xffffffffu, p2, o);
        }
        if (lane == 0) redp[warp] = make_float2(p1, p2);
        __syncthreads();
        // ---- warp 0: reduce 8 partials, both reciprocals, broadcast ----
        if (warp == 0) {
            float2 q = redp[lane & 7];
            float s1 = q.x, s2 = q.y;
#pragma unroll
            for (int o = 4; o > 0; o >>= 1) {
                s1 += __shfl_xor_sync(0xffffffffu, s1, o);
                s2 += __shfl_xor_sync(0xffffffffu, s2, o);
            }
            if (lane == 0) {
                float inv1 = __frcp_rn(s1);
                float S2   = fmaf(-s2, inv1, s1);   // S - Q/S = Σ w(1 - w/S)
                bc = make_float2(inv1, __frcp_rn(S2));
            }
        }
        __syncthreads();
        const float inv1 = bc.x;
        const float inv2 = bc.y;

        const u64 iv1  = pk2(inv1, inv1);
        const u64 niv1 = pk2(-inv1, -inv1);
        const u64 iv2  = pk2(inv2, inv2);
        const u64 niv2 = pk2(-inv2, -inv2);

        // ---- step A (uses 1/S): 3 packed fma-pipe instrs per pair, no clamp ----
#pragma unroll
        for (int i = 0; i < 8; i++) {
            u64 t2 = fma2(w2[i], niv1, ones2);       // 1 - w/S  (>= -2ulp)
            kh2[i] = fma2(w2[i], iv1, kh2[i]);       // khot += w/S
            w2[i]  = mul2(w2[i], t2);
        }
        // ---- step B (uses 1/S2) ----
#pragma unroll
        for (int i = 0; i < 8; i++) {
            u64 t2 = fma2(w2[i], niv2, ones2);
            kh2[i] = fma2(w2[i], iv2, kh2[i]);
            w2[i]  = mul2(w2[i], t2);
        }
    }

    // ---- store khot ----
#pragma unroll
    for (int j = 0; j < 4; j++) {
        float4 r4;
        upk2(kh2[2*j],   r4.x, r4.y);
        upk2(kh2[2*j+1], r4.z, r4.w);
        o4[tid + j * THREADS] = r4;
    }
}

extern "C" void kernel_launch(void* const* d_in, const int* in_sizes, int n_in,
                              void* d_out, int out_size)
{
    const float* scores = (const float*)d_in[0];
    const float* gnoise = (const float*)d_in[1];
    float* out = (float*)d_out;

    const int total = in_sizes[0];        // 4 * 2048 * 4096
    const int rows  = total / NCOL;       // 8192

    subset_op_kernel<<<rows, THREADS>>>(scores, gnoise, out);
}

// round 12
// speedup vs baseline: 2.5452x; 1.0311x over previous
#include <cuda_runtime.h>
#include <cuda_bf16.h>

#define NCOL    4096
#define THREADS 256

typedef unsigned long long u64;

// ---- Blackwell packed f32x2 helpers (one instruction, two fp32 lanes) ----
__device__ __forceinline__ u64 pk2(float lo, float hi) {
    u64 r; asm("mov.b64 %0, {%1, %2};" : "=l"(r) : "f"(lo), "f"(hi)); return r;
}
__device__ __forceinline__ void upk2(u64 v, float& lo, float& hi) {
    asm("mov.b64 {%0, %1}, %2;" : "=f"(lo), "=f"(hi) : "l"(v));
}
__device__ __forceinline__ u64 fma2(u64 a, u64 b, u64 c) {
    u64 d; asm("fma.rn.f32x2 %0, %1, %2, %3;" : "=l"(d) : "l"(a), "l"(b), "l"(c)); return d;
}
__device__ __forceinline__ u64 mul2(u64 a, u64 b) {
    u64 d; asm("mul.rn.f32x2 %0, %1, %2;" : "=l"(d) : "l"(a), "l"(b)); return d;
}
__device__ __forceinline__ u64 add2(u64 a, u64 b) {
    u64 d; asm("add.rn.f32x2 %0, %1, %2;" : "=l"(d) : "l"(a), "l"(b)); return d;
}
__device__ __forceinline__ float rcp_fast(float x) {
    float y; asm("rcp.approx.f32 %0, %1;" : "=f"(y) : "f"(x)); return y;
}

// One CTA (256 threads) per row of 4096: 16 elements/thread in 8 packed f32x2
// registers. K=16 softmax iterations as 8 fused rounds (S2 = S - Q/S).
// ONE barrier per round: warps post packed (p1,p2) partials to shared; every
// warp re-reduces all 8 partials itself via 4x broadcast LDS.128 + add2 tree
// and computes both reciprocals locally (rcp.approx). Partials are
// parity-double-buffered to avoid write-after-read across the single barrier.
__global__ void __launch_bounds__(THREADS, 4)
subset_op_kernel(const float* __restrict__ scores,
                 const float* __restrict__ gnoise,
                 float* __restrict__ out)
{
    const int tid  = threadIdx.x;
    const int lane = tid & 31;
    const int warp = tid >> 5;
    const size_t rb = (size_t)blockIdx.x * (NCOL / 4);
    const float4* s4 = reinterpret_cast<const float4*>(scores) + rb;
    const float4* g4 = reinterpret_cast<const float4*>(gnoise) + rb;
    float4*       o4 = reinterpret_cast<float4*>(out)          + rb;

    __shared__ float redm[8];
    __shared__ __align__(16) u64 redp[2][8];

    // ---- load s0 = scores + g : 16 elements per thread ----
    float s[16];
#pragma unroll
    for (int j = 0; j < 4; j++) {
        float4 a = s4[tid + j * THREADS];
        float4 b = g4[tid + j * THREADS];
        s[4*j+0] = a.x + b.x; s[4*j+1] = a.y + b.y;
        s[4*j+2] = a.z + b.z; s[4*j+3] = a.w + b.w;
    }

    // ---- row max: one barrier, every warp self-reduces the 8 partial maxes ----
    float m = s[0];
#pragma unroll
    for (int j = 1; j < 16; j++) m = fmaxf(m, s[j]);
#pragma unroll
    for (int o = 16; o > 0; o >>= 1) m = fmaxf(m, __shfl_xor_sync(0xffffffffu, m, o));
    if (lane == 0) redm[warp] = m;
    __syncthreads();
    {
        float4 ma = reinterpret_cast<const float4*>(redm)[0];
        float4 mb = reinterpret_cast<const float4*>(redm)[1];
        m = fmaxf(fmaxf(fmaxf(ma.x, ma.y), fmaxf(ma.z, ma.w)),
                  fmaxf(fmaxf(mb.x, mb.y), fmaxf(mb.z, mb.w)));
    }

    // ---- w = exp(s0 - M), pack into 8 f32x2 registers ----
    u64 w2[8], kh2[8];
#pragma unroll
    for (int i = 0; i < 8; i++) {
        w2[i]  = pk2(__expf(s[2*i] - m), __expf(s[2*i+1] - m));
        kh2[i] = 0ull;   // (0.f, 0.f)
    }

    const u64 ones2 = pk2(1.f, 1.f);

#pragma unroll
    for (int r = 0; r < 8; r++) {
        // ---- packed moments: p1 = Σw, p2 = Σw² ----
        u64 a1 = add2(w2[0], w2[1]);
        u64 a2 = add2(w2[2], w2[3]);
        u64 a3 = add2(w2[4], w2[5]);
        u64 a4 = add2(w2[6], w2[7]);
        u64 p1p = add2(add2(a1, a2), add2(a3, a4));

        u64 q1 = mul2(w2[0], w2[0]);
        q1 = fma2(w2[1], w2[1], q1);
        q1 = fma2(w2[2], w2[2], q1);
        q1 = fma2(w2[3], w2[3], q1);
        q1 = fma2(w2[4], w2[4], q1);
        q1 = fma2(w2[5], w2[5], q1);
        q1 = fma2(w2[6], w2[6], q1);
        u64 p2p = fma2(w2[7], w2[7], q1);

        // horizontal: pp = (p1, p2) packed in one u64
        float p1a, p1b, p2a, p2b;
        upk2(p1p, p1a, p1b);
        upk2(p2p, p2a, p2b);
        u64 pp = pk2(p1a + p1b, p2a + p2b);

        // ---- intra-warp reduce on the packed pair: 2 SHFL + 1 add2 per level ----
#pragma unroll
        for (int o = 16; o > 0; o >>= 1) {
            u64 other = __shfl_xor_sync(0xffffffffu, pp, o);
            pp = add2(pp, other);
        }
        if (lane == 0) redp[r & 1][warp] = pp;
        __syncthreads();

        // ---- every warp: 4x broadcast LDS.128 + add2 tree over 8 partials ----
        const ulonglong2* rp = reinterpret_cast<const ulonglong2*>(redp[r & 1]);
        ulonglong2 v0 = rp[0], v1 = rp[1], v2v = rp[2], v3 = rp[3];
        u64 t0 = add2(v0.x, v0.y);
        u64 t1 = add2(v1.x, v1.y);
        u64 t2s = add2(v2v.x, v2v.y);
        u64 t3 = add2(v3.x, v3.y);
        u64 tot = add2(add2(t0, t1), add2(t2s, t3));

        float s1, sq;
        upk2(tot, s1, sq);
        const float inv1 = rcp_fast(s1);
        const float S2   = fmaf(-sq, inv1, s1);   // S - Q/S = Σ w(1 - w/S)
        const float inv2 = rcp_fast(S2);

        const u64 iv1  = pk2(inv1, inv1);
        const u64 niv1 = pk2(-inv1, -inv1);
        const u64 iv2  = pk2(inv2, inv2);
        const u64 niv2 = pk2(-inv2, -inv2);

        // ---- step A (uses 1/S): pure packed, no clamp ----
#pragma unroll
        for (int i = 0; i < 8; i++) {
            u64 t2 = fma2(w2[i], niv1, ones2);       // 1 - w/S
            kh2[i] = fma2(w2[i], iv1, kh2[i]);       // khot += w/S
            w2[i]  = mul2(w2[i], t2);
        }
        // ---- step B (uses 1/S2) ----
#pragma unroll
        for (int i = 0; i < 8; i++) {
            u64 t2 = fma2(w2[i], niv2, ones2);
            kh2[i] = fma2(w2[i], iv2, kh2[i]);
            w2[i]  = mul2(w2[i], t2);
        }
    }

    // ---- store khot ----
#pragma unroll
    for (int j = 0; j < 4; j++) {
        float4 r4;
        upk2(kh2[2*j],   r4.x, r4.y);
        upk2(kh2[2*j+1], r4.z, r4.w);
        o4[tid + j * THREADS] = r4;
    }
}

extern "C" void kernel_launch(void* const* d_in, const int* in_sizes, int n_in,
                              void* d_out, int out_size)
{
    const float* scores = (const float*)d_in[0];
    const float* gnoise = (const float*)d_in[1];
    float* out = (float*)d_out;

    const int total = in_sizes[0];        // 4 * 2048 * 4096
    const int rows  = total / NCOL;       // 8192

    subset_op_kernel<<<rows, THREADS>>>(scores, gnoise, out);
}